// round 13
// baseline (speedup 1.0000x reference)
#include <cuda_runtime.h>

// ---------------------------------------------------------------------------
// GNN VAE on GB300. CSR-by-dst build (hierarchical scan), gather propagation
// (no float atomics). Decoder GCN: propagate-then-transform.
// R12: prop_hd merged into gemm2 (warp gathers 8 nodes' pd rows, then
// multiplies by W_dec from smem). One fewer launch; no g_pd round-trip.
// Launch spine otherwise identical to R5/R11 (238.1/238.4us).
// ---------------------------------------------------------------------------

#define MAXN 50048
#define MAXE 800256

typedef unsigned long long u64;

__device__ __forceinline__ u64 pack2(float x, float y) {
    u64 r; asm("mov.b64 %0, {%1,%2};" : "=l"(r) : "f"(x), "f"(y)); return r;
}
__device__ __forceinline__ u64 packb(int wbits) {
    float w = __int_as_float(wbits);
    u64 r; asm("mov.b64 %0, {%1,%1};" : "=l"(r) : "f"(w)); return r;
}
__device__ __forceinline__ void ffma2(u64 &d, u64 a, u64 b) {
    asm("fma.rn.f32x2 %0, %1, %2, %0;" : "+l"(d) : "l"(a), "l"(b));
}
__device__ __forceinline__ u64 add2(u64 a, u64 b) {
    u64 r; asm("add.rn.f32x2 %0, %1, %2;" : "=l"(r) : "l"(a), "l"(b)); return r;
}

__device__ int   g_cnt[MAXN];
__device__ int   g_cursor[MAXN];
__device__ int   g_rowptr[MAXN + 1];
__device__ int   g_bsum[128];
__device__ int   g_boff[128];
__device__ float g_dinv[MAXN];
__device__ __align__(16) int2  g_csr[MAXE];               // {src, weight bits}
__device__ __align__(256) float g_h1[(size_t)MAXN * 64];  // x @ W_enc_gnn
__device__ __align__(256) float g_hd[(size_t)MAXN * 64];  // relu(z @ W_dec_fc + b)

// ---------------------------------------------------------------- init / deg
__global__ void k_init(int n) {
    int i = blockIdx.x * blockDim.x + threadIdx.x;
    if (i < n) g_cnt[i] = 0;
}

__global__ void k_count(const int* __restrict__ dst, int E) {
    int i = blockIdx.x * blockDim.x + threadIdx.x;
    if (i < E) atomicAdd(&g_cnt[dst[i]], 1);
}

// ----------------------------------------------------- hierarchical scan
__global__ void k_scan_a(int n) {
    __shared__ int wsum[32];
    int t = threadIdx.x;
    int gid = blockIdx.x * 1024 + t;
    int lane = t & 31, w = t >> 5;
    int v = (gid < n) ? g_cnt[gid] : 0;
    int s = v;
#pragma unroll
    for (int o = 1; o < 32; o <<= 1) {
        int u = __shfl_up_sync(0xFFFFFFFFu, s, o);
        if (lane >= o) s += u;
    }
    if (lane == 31) wsum[w] = s;
    __syncthreads();
    if (w == 0) {
        int ws = wsum[lane];
#pragma unroll
        for (int o = 1; o < 32; o <<= 1) {
            int u = __shfl_up_sync(0xFFFFFFFFu, ws, o);
            if (lane >= o) ws += u;
        }
        wsum[lane] = ws;
    }
    __syncthreads();
    int incl = s + (w > 0 ? wsum[w - 1] : 0);
    if (gid < n) g_rowptr[gid + 1] = incl;
    if (t == 1023) g_bsum[blockIdx.x] = incl;
}

__global__ void k_scan_b(int nblk) {
    __shared__ int sh[128];
    int t = threadIdx.x;
    sh[t] = (t < nblk) ? g_bsum[t] : 0;
    __syncthreads();
#pragma unroll
    for (int o = 1; o < 128; o <<= 1) {
        int u = (t >= o) ? sh[t - o] : 0;
        __syncthreads();
        sh[t] += u;
        __syncthreads();
    }
    g_boff[t] = (t > 0) ? sh[t - 1] : 0;
    if (t == 0) g_rowptr[0] = 0;
}

__global__ void k_scan_c(int n) {
    int i = blockIdx.x * blockDim.x + threadIdx.x;
    if (i >= n) return;
    g_rowptr[i + 1] += g_boff[i >> 10];
    g_dinv[i] = rsqrtf((float)(g_cnt[i] + 1));  // +1 self loop
    g_cursor[i] = 0;
}

__global__ void k_fill(const int* __restrict__ src, const int* __restrict__ dst, int E) {
    int i = blockIdx.x * blockDim.x + threadIdx.x;
    if (i >= E) return;
    int s = src[i], d = dst[i];
    int pos = atomicAdd(&g_cursor[d], 1);
    float w = g_dinv[s] * g_dinv[d];
    g_csr[g_rowptr[d] + pos] = make_int2(s, __float_as_int(w));
}

// ---------------------------------------------------- GEMM1: [N,256]@[256,64]
__global__ void k_gemm1(const float* __restrict__ x, const float* __restrict__ W, int n) {
    extern __shared__ float Wsm[];  // 256*64 floats
    for (int i = threadIdx.x; i < 256 * 64 / 4; i += blockDim.x)
        ((float4*)Wsm)[i] = ((const float4*)W)[i];
    __syncthreads();

    int row = blockIdx.x * blockDim.x + threadIdx.x;
    if (row >= n) return;

    u64 acc[32];
#pragma unroll
    for (int j = 0; j < 32; j++) acc[j] = 0ull;

    const float4* xr = (const float4*)(x + (size_t)row * 256);
    for (int k4 = 0; k4 < 64; k4++) {
        float4 xv = __ldg(xr + k4);
#pragma unroll
        for (int kk = 0; kk < 4; kk++) {
            float xk = (kk == 0) ? xv.x : (kk == 1) ? xv.y : (kk == 2) ? xv.z : xv.w;
            u64 xx = pack2(xk, xk);
            const ulonglong2* wrow = (const ulonglong2*)(Wsm + (k4 * 4 + kk) * 64);
#pragma unroll
            for (int j = 0; j < 16; j++) {
                ulonglong2 w = wrow[j];
                ffma2(acc[2 * j],     xx, w.x);
                ffma2(acc[2 * j + 1], xx, w.y);
            }
        }
    }
    ulonglong2* o = (ulonglong2*)(g_h1 + (size_t)row * 64);
#pragma unroll
    for (int j = 0; j < 16; j++) { ulonglong2 t; t.x = acc[2 * j]; t.y = acc[2 * j + 1]; o[j] = t; }
}

// --------------------------- gather core (64-d, warp-per-node, x2) ---------
__device__ __forceinline__ u64 gather64(const float* __restrict__ feat,
                                        int gw, int lane, u64 init) {
    u64 acc = init;
    int e = g_rowptr[gw], end = g_rowptr[gw + 1];
    for (; e + 2 <= end; e += 2) {
        int2 e0 = g_csr[e], e1 = g_csr[e + 1];
        u64 v0 = ((const u64*)(feat + (size_t)e0.x * 64))[lane];
        u64 v1 = ((const u64*)(feat + (size_t)e1.x * 64))[lane];
        ffma2(acc, v0, packb(e0.y));
        ffma2(acc, v1, packb(e1.y));
    }
    if (e < end) {
        int2 e0 = g_csr[e];
        u64 v0 = ((const u64*)(feat + (size_t)e0.x * 64))[lane];
        ffma2(acc, v0, packb(e0.y));
    }
    return acc;
}

// ------------- fused: prop1 (gather, 64-d, +bias +relu) THEN encoder MLPs
__global__ void k_prop1_mlp(const float* __restrict__ b,
                            const float* __restrict__ Wef, const float* __restrict__ bef,
                            const float* __restrict__ Wdf, const float* __restrict__ bdf,
                            const float* __restrict__ Wc,  const float* __restrict__ bc,
                            float* __restrict__ out_z, float* __restrict__ out_pr, int n) {
    __shared__ float o_s[8][64];
    __shared__ float z_s[8][32];
    int wl = threadIdx.x >> 5, lane = threadIdx.x & 31;
    int gw = (blockIdx.x * blockDim.x + threadIdx.x) >> 5;
    if (gw >= n) return;

    float di = g_dinv[gw];
    u64 dii = pack2(di * di, di * di);
    u64 self = ((const u64*)(g_h1 + (size_t)gw * 64))[lane];
    u64 init = 0ull;
    ffma2(init, self, dii);
    u64 acc = gather64(g_h1, gw, lane, init);

    float2 r = *(float2*)&acc;
    float2 bf = ((const float2*)b)[lane];
    r.x = fmaxf(r.x + bf.x, 0.f);
    r.y = fmaxf(r.y + bf.y, 0.f);
    o_s[wl][2 * lane]     = r.x;
    o_s[wl][2 * lane + 1] = r.y;
    __syncwarp();

    float s = bef[lane];
#pragma unroll
    for (int k = 0; k < 64; k++) s += o_s[wl][k] * Wef[k * 32 + lane];
    z_s[wl][lane] = s;
    out_z[(size_t)gw * 32 + lane] = s;
    __syncwarp();

    float c0 = bdf[lane], c1 = bdf[lane + 32];
#pragma unroll
    for (int k = 0; k < 32; k++) {
        float zk = z_s[wl][k];
        c0 += zk * Wdf[k * 64 + lane];
        c1 += zk * Wdf[k * 64 + lane + 32];
    }
    g_hd[(size_t)gw * 64 + lane]      = fmaxf(c0, 0.f);
    g_hd[(size_t)gw * 64 + lane + 32] = fmaxf(c1, 0.f);

    if (lane < 3) {
        float p = bc[lane];
#pragma unroll
        for (int k = 0; k < 32; k++) p += z_s[wl][k] * Wc[k * 3 + lane];
        out_pr[(size_t)gw * 3 + lane] = p;
    }
}

// ---------- merged prop_hd + GEMM2: x_recon = (A_norm hd) @ W_dec + b_dec
// Warp gathers 8 nodes' propagated rows (hv[j], float2/lane), then multiplies
// by W_dec from smem (8-row amortization as before). No g_pd round-trip.
#define G2R 8
__global__ void k_prop_gemm2(const float* __restrict__ W, const float* __restrict__ b,
                             float* __restrict__ outx, int n) {
    extern __shared__ float Wsm[];  // 64*256 floats
    for (int i = threadIdx.x; i < 64 * 256 / 4; i += blockDim.x)
        ((float4*)Wsm)[i] = ((const float4*)W)[i];
    __syncthreads();

    int gw = (blockIdx.x * blockDim.x + threadIdx.x) >> 5;
    int lane = threadIdx.x & 31;
    int r0 = gw * G2R;
    if (r0 >= n) return;

    // ---- gather phase: hv[j] = (A_norm hd)[row r0+j], float2 per lane
    float2 hv[G2R];
#pragma unroll
    for (int j = 0; j < G2R; j++) {
        int row = r0 + j;
        if (row < n) {
            float di = g_dinv[row];
            u64 dii = pack2(di * di, di * di);
            u64 self = ((const u64*)(g_hd + (size_t)row * 64))[lane];
            u64 init = 0ull;
            ffma2(init, self, dii);
            u64 acc = gather64(g_hd, row, lane, init);
            hv[j] = *(float2*)&acc;
        } else {
            hv[j] = make_float2(0.f, 0.f);
        }
    }

    // ---- multiply phase (identical to previous gemm2)
    u64 acc[G2R][4];
#pragma unroll
    for (int j = 0; j < G2R; j++)
#pragma unroll
        for (int c = 0; c < 4; c++) acc[j][c] = 0ull;

    const ulonglong2* W2 = (const ulonglong2*)Wsm;  // 64 ulonglong2 per k-row
#pragma unroll
    for (int k = 0; k < 64; k++) {
        ulonglong2 w0 = W2[k * 64 + lane];
        ulonglong2 w1 = W2[k * 64 + 32 + lane];
#pragma unroll
        for (int j = 0; j < G2R; j++) {
            float hk = __shfl_sync(0xFFFFFFFFu, (k & 1) ? hv[j].y : hv[j].x, k >> 1);
            u64 hh = pack2(hk, hk);
            ffma2(acc[j][0], hh, w0.x);
            ffma2(acc[j][1], hh, w0.y);
            ffma2(acc[j][2], hh, w1.x);
            ffma2(acc[j][3], hh, w1.y);
        }
    }
    const ulonglong2* b2 = (const ulonglong2*)b;
    ulonglong2 b0 = b2[lane], b1 = b2[lane + 32];
#pragma unroll
    for (int j = 0; j < G2R; j++) {
        int row = r0 + j;
        if (row >= n) break;
        ulonglong2 t0, t1;
        t0.x = add2(acc[j][0], b0.x); t0.y = add2(acc[j][1], b0.y);
        t1.x = add2(acc[j][2], b1.x); t1.y = add2(acc[j][3], b1.y);
        ulonglong2* o = (ulonglong2*)(outx + (size_t)row * 256);
        o[lane] = t0;
        o[lane + 32] = t1;
    }
}

// ---------------------------------------------------------------------------
extern "C" void kernel_launch(void* const* d_in, const int* in_sizes, int n_in,
                              void* d_out, int out_size) {
    const float* x     = (const float*)d_in[0];
    const int*   ei    = (const int*)d_in[1];
    // d_in[2] = edge_attr (unused by reference)
    const float* W_enc = (const float*)d_in[3];
    const float* b_enc = (const float*)d_in[4];
    const float* W_ef  = (const float*)d_in[5];
    const float* b_ef  = (const float*)d_in[6];
    const float* W_df  = (const float*)d_in[7];
    const float* b_df  = (const float*)d_in[8];
    const float* W_dec = (const float*)d_in[9];
    const float* b_dec = (const float*)d_in[10];
    const float* W_c   = (const float*)d_in[11];
    const float* b_c   = (const float*)d_in[12];

    int N = in_sizes[0] / 256;
    int E = in_sizes[1] / 2;
    const int* src = ei;
    const int* dst = ei + E;

    float* out    = (float*)d_out;
    float* out_xr = out;
    float* out_z  = out + (size_t)N * 256;
    float* out_pr = out_z + (size_t)N * 32;

    cudaFuncSetAttribute(k_gemm1, cudaFuncAttributeMaxDynamicSharedMemorySize, 65536);
    cudaFuncSetAttribute(k_prop_gemm2, cudaFuncAttributeMaxDynamicSharedMemorySize, 65536);

    int gbN    = (N + 255) / 256;
    int gbE    = (E + 255) / 256;
    int gbW    = (N + 7) / 8;                   // warp-per-node, 8 warps/block
    int nwarp2 = (N + G2R - 1) / G2R;
    int gbG2   = (nwarp2 * 32 + 255) / 256;
    int nblk   = (N + 1023) / 1024;

    k_init      <<<gbN, 256>>>(N);
    k_count     <<<gbE, 256>>>(dst, E);
    k_scan_a    <<<nblk, 1024>>>(N);
    k_scan_b    <<<1, 128>>>(nblk);
    k_scan_c    <<<gbN, 256>>>(N);
    k_fill      <<<gbE, 256>>>(src, dst, E);
    k_gemm1     <<<gbN, 256, 65536>>>(x, W_enc, N);
    k_prop1_mlp <<<gbW, 256>>>(b_enc, W_ef, b_ef, W_df, b_df, W_c, b_c, out_z, out_pr, N);
    k_prop_gemm2<<<gbG2, 256, 65536>>>(W_dec, b_dec, out_xr, N);
}

// round 16
// speedup vs baseline: 1.0877x; 1.0877x over previous
#include <cuda_runtime.h>

// ---------------------------------------------------------------------------
// GNN VAE on GB300. CSR-by-dst build, gather propagation (no float atomics).
// Decoder GCN: propagate-then-transform. GEMM2 8 rows/warp. Single stream.
// R14 = R11 spine with two launch eliminations:
//   - k_scan_b dropped: scan_c blocks recompute chunk offset via warp-reduce
//   - k_init dropped:   prop1_mlp re-zeroes g_cnt (post-consumption)
// ---------------------------------------------------------------------------

#define MAXN 50048
#define MAXE 800256

typedef unsigned long long u64;

__device__ __forceinline__ u64 pack2(float x, float y) {
    u64 r; asm("mov.b64 %0, {%1,%2};" : "=l"(r) : "f"(x), "f"(y)); return r;
}
__device__ __forceinline__ u64 packb(int wbits) {
    float w = __int_as_float(wbits);
    u64 r; asm("mov.b64 %0, {%1,%1};" : "=l"(r) : "f"(w)); return r;
}
__device__ __forceinline__ void ffma2(u64 &d, u64 a, u64 b) {
    asm("fma.rn.f32x2 %0, %1, %2, %0;" : "+l"(d) : "l"(a), "l"(b));
}
__device__ __forceinline__ u64 add2(u64 a, u64 b) {
    u64 r; asm("add.rn.f32x2 %0, %1, %2;" : "=l"(r) : "l"(a), "l"(b)); return r;
}

__device__ int   g_cnt[MAXN];     // zero at rest; consumed by scan, re-zeroed by prop1_mlp
__device__ int   g_cursor[MAXN];
__device__ int   g_rowptr[MAXN + 1];
__device__ int   g_bsum[128];
__device__ float g_dinv[MAXN];
__device__ __align__(16) int2  g_csr[MAXE];               // {src, weight bits}
__device__ __align__(256) float g_h1[(size_t)MAXN * 64];  // x @ W_enc_gnn
__device__ __align__(256) float g_hd[(size_t)MAXN * 64];  // relu(z @ W_dec_fc + b)
__device__ __align__(256) float g_pd[(size_t)MAXN * 64];  // A_norm @ hd

// ---------------------------------------------------------------- count
__global__ void k_count(const int* __restrict__ dst, int E) {
    int i = blockIdx.x * blockDim.x + threadIdx.x;
    if (i < E) atomicAdd(&g_cnt[dst[i]], 1);
}

// ------------------------------------- scan A: per-1024-chunk local scan
__global__ void k_scan_a(int n) {
    __shared__ int wsum[32];
    int t = threadIdx.x;
    int gid = blockIdx.x * 1024 + t;
    int lane = t & 31, w = t >> 5;
    int v = (gid < n) ? g_cnt[gid] : 0;
    int s = v;
#pragma unroll
    for (int o = 1; o < 32; o <<= 1) {
        int u = __shfl_up_sync(0xFFFFFFFFu, s, o);
        if (lane >= o) s += u;
    }
    if (lane == 31) wsum[w] = s;
    __syncthreads();
    if (w == 0) {
        int ws = wsum[lane];
#pragma unroll
        for (int o = 1; o < 32; o <<= 1) {
            int u = __shfl_up_sync(0xFFFFFFFFu, ws, o);
            if (lane >= o) ws += u;
        }
        wsum[lane] = ws;
    }
    __syncthreads();
    int incl = s + (w > 0 ? wsum[w - 1] : 0);
    if (gid < n) g_rowptr[gid + 1] = incl;
    if (t == 1023) g_bsum[blockIdx.x] = incl;
}

// ---- scan C: each 256-thread block lies in ONE 1024-chunk; warp 0 reduces
// g_bsum[0..chunk) for the offset. Also dinv + cursor zero. No scan_b kernel.
__global__ void k_scan_c(int n, int nblk) {
    __shared__ int s_off;
    int t = threadIdx.x;
    int chunk = (int)(blockIdx.x >> 2);    // (blockIdx.x*256)>>10
    if (t < 32) {
        int acc = 0;
        if (t < chunk && t < nblk)                 acc += g_bsum[t];
        if (t + 32 < chunk && t + 32 < nblk)       acc += g_bsum[t + 32];
        if (t + 64 < chunk && t + 64 < nblk)       acc += g_bsum[t + 64];
        if (t + 96 < chunk && t + 96 < nblk)       acc += g_bsum[t + 96];
#pragma unroll
        for (int o = 16; o > 0; o >>= 1)
            acc += __shfl_down_sync(0xFFFFFFFFu, acc, o);
        if (t == 0) s_off = acc;
    }
    __syncthreads();
    int off = s_off;
    int i = blockIdx.x * blockDim.x + t;
    if (i >= n) return;
    if (i == 0) g_rowptr[0] = 0;
    g_rowptr[i + 1] += off;
    g_dinv[i] = rsqrtf((float)(g_cnt[i] + 1));  // +1 self loop
    g_cursor[i] = 0;
}

__global__ void k_fill(const int* __restrict__ src, const int* __restrict__ dst, int E) {
    int i = blockIdx.x * blockDim.x + threadIdx.x;
    if (i >= E) return;
    int s = src[i], d = dst[i];
    int pos = atomicAdd(&g_cursor[d], 1);
    float w = g_dinv[s] * g_dinv[d];
    g_csr[g_rowptr[d] + pos] = make_int2(s, __float_as_int(w));
}

// ---------------------------------------------------- GEMM1: [N,256]@[256,64]
__global__ void k_gemm1(const float* __restrict__ x, const float* __restrict__ W, int n) {
    extern __shared__ float Wsm[];  // 256*64 floats
    for (int i = threadIdx.x; i < 256 * 64 / 4; i += blockDim.x)
        ((float4*)Wsm)[i] = ((const float4*)W)[i];
    __syncthreads();

    int row = blockIdx.x * blockDim.x + threadIdx.x;
    if (row >= n) return;

    u64 acc[32];
#pragma unroll
    for (int j = 0; j < 32; j++) acc[j] = 0ull;

    const float4* xr = (const float4*)(x + (size_t)row * 256);
    for (int k4 = 0; k4 < 64; k4++) {
        float4 xv = __ldg(xr + k4);
#pragma unroll
        for (int kk = 0; kk < 4; kk++) {
            float xk = (kk == 0) ? xv.x : (kk == 1) ? xv.y : (kk == 2) ? xv.z : xv.w;
            u64 xx = pack2(xk, xk);
            const ulonglong2* wrow = (const ulonglong2*)(Wsm + (k4 * 4 + kk) * 64);
#pragma unroll
            for (int j = 0; j < 16; j++) {
                ulonglong2 w = wrow[j];
                ffma2(acc[2 * j],     xx, w.x);
                ffma2(acc[2 * j + 1], xx, w.y);
            }
        }
    }
    ulonglong2* o = (ulonglong2*)(g_h1 + (size_t)row * 64);
#pragma unroll
    for (int j = 0; j < 16; j++) { ulonglong2 t; t.x = acc[2 * j]; t.y = acc[2 * j + 1]; o[j] = t; }
}

// --------------------------- gather core (64-d, warp-per-node, x2) ---------
__device__ __forceinline__ u64 gather64(const float* __restrict__ feat,
                                        int gw, int lane, u64 init) {
    u64 acc = init;
    int e = g_rowptr[gw], end = g_rowptr[gw + 1];
    for (; e + 2 <= end; e += 2) {
        int2 e0 = g_csr[e], e1 = g_csr[e + 1];
        u64 v0 = ((const u64*)(feat + (size_t)e0.x * 64))[lane];
        u64 v1 = ((const u64*)(feat + (size_t)e1.x * 64))[lane];
        ffma2(acc, v0, packb(e0.y));
        ffma2(acc, v1, packb(e1.y));
    }
    if (e < end) {
        int2 e0 = g_csr[e];
        u64 v0 = ((const u64*)(feat + (size_t)e0.x * 64))[lane];
        ffma2(acc, v0, packb(e0.y));
    }
    return acc;
}

// ------------- fused: prop1 (gather, 64-d, +bias +relu) THEN encoder MLPs
// Also re-zeroes g_cnt[gw] (consumed by scan_c earlier) for the next replay.
__global__ void k_prop1_mlp(const float* __restrict__ b,
                            const float* __restrict__ Wef, const float* __restrict__ bef,
                            const float* __restrict__ Wdf, const float* __restrict__ bdf,
                            const float* __restrict__ Wc,  const float* __restrict__ bc,
                            float* __restrict__ out_z, float* __restrict__ out_pr, int n) {
    __shared__ float o_s[8][64];
    __shared__ float z_s[8][32];
    int wl = threadIdx.x >> 5, lane = threadIdx.x & 31;
    int gw = (blockIdx.x * blockDim.x + threadIdx.x) >> 5;
    if (gw >= n) return;

    if (lane == 0) g_cnt[gw] = 0;   // replaces k_init (for next replay)

    float di = g_dinv[gw];
    u64 dii = pack2(di * di, di * di);
    u64 self = ((const u64*)(g_h1 + (size_t)gw * 64))[lane];
    u64 init = 0ull;
    ffma2(init, self, dii);
    u64 acc = gather64(g_h1, gw, lane, init);

    float2 r = *(float2*)&acc;
    float2 bf = ((const float2*)b)[lane];
    r.x = fmaxf(r.x + bf.x, 0.f);
    r.y = fmaxf(r.y + bf.y, 0.f);
    o_s[wl][2 * lane]     = r.x;
    o_s[wl][2 * lane + 1] = r.y;
    __syncwarp();

    float s = bef[lane];
#pragma unroll
    for (int k = 0; k < 64; k++) s += o_s[wl][k] * Wef[k * 32 + lane];
    z_s[wl][lane] = s;
    out_z[(size_t)gw * 32 + lane] = s;
    __syncwarp();

    float c0 = bdf[lane], c1 = bdf[lane + 32];
#pragma unroll
    for (int k = 0; k < 32; k++) {
        float zk = z_s[wl][k];
        c0 += zk * Wdf[k * 64 + lane];
        c1 += zk * Wdf[k * 64 + lane + 32];
    }
    g_hd[(size_t)gw * 64 + lane]      = fmaxf(c0, 0.f);
    g_hd[(size_t)gw * 64 + lane + 32] = fmaxf(c1, 0.f);

    if (lane < 3) {
        float p = bc[lane];
#pragma unroll
        for (int k = 0; k < 32; k++) p += z_s[wl][k] * Wc[k * 3 + lane];
        out_pr[(size_t)gw * 3 + lane] = p;
    }
}

// ---------------------------- prop_hd: gather propagation of hd (dim 64)
__global__ void k_prop_hd(int n) {
    int gw = (blockIdx.x * blockDim.x + threadIdx.x) >> 5;
    int lane = threadIdx.x & 31;
    if (gw >= n) return;
    float di = g_dinv[gw];
    u64 dii = pack2(di * di, di * di);
    u64 self = ((const u64*)(g_hd + (size_t)gw * 64))[lane];
    u64 init = 0ull;
    ffma2(init, self, dii);
    u64 acc = gather64(g_hd, gw, lane, init);
    ((u64*)(g_pd + (size_t)gw * 64))[lane] = acc;
}

// ------------------- GEMM2: x_recon = (A_norm hd) @ W_dec + b_dec
// 8 rows per warp: W smem reads amortized 8x; pd broadcast via shfl.
#define G2R 8
__global__ void k_gemm2(const float* __restrict__ W, const float* __restrict__ b,
                        float* __restrict__ outx, int n) {
    extern __shared__ float Wsm[];  // 64*256 floats
    for (int i = threadIdx.x; i < 64 * 256 / 4; i += blockDim.x)
        ((float4*)Wsm)[i] = ((const float4*)W)[i];
    __syncthreads();

    int gw = (blockIdx.x * blockDim.x + threadIdx.x) >> 5;
    int lane = threadIdx.x & 31;
    int r0 = gw * G2R;
    if (r0 >= n) return;

    float2 hv[G2R];
#pragma unroll
    for (int j = 0; j < G2R; j++)
        hv[j] = ((const float2*)(g_pd + (size_t)(r0 + j) * 64))[lane];

    u64 acc[G2R][4];
#pragma unroll
    for (int j = 0; j < G2R; j++)
#pragma unroll
        for (int c = 0; c < 4; c++) acc[j][c] = 0ull;

    const ulonglong2* W2 = (const ulonglong2*)Wsm;
#pragma unroll
    for (int k = 0; k < 64; k++) {
        ulonglong2 w0 = W2[k * 64 + lane];
        ulonglong2 w1 = W2[k * 64 + 32 + lane];
#pragma unroll
        for (int j = 0; j < G2R; j++) {
            float hk = __shfl_sync(0xFFFFFFFFu, (k & 1) ? hv[j].y : hv[j].x, k >> 1);
            u64 hh = pack2(hk, hk);
            ffma2(acc[j][0], hh, w0.x);
            ffma2(acc[j][1], hh, w0.y);
            ffma2(acc[j][2], hh, w1.x);
            ffma2(acc[j][3], hh, w1.y);
        }
    }
    const ulonglong2* b2 = (const ulonglong2*)b;
    ulonglong2 b0 = b2[lane], b1 = b2[lane + 32];
#pragma unroll
    for (int j = 0; j < G2R; j++) {
        int row = r0 + j;
        if (row >= n) break;
        ulonglong2 t0, t1;
        t0.x = add2(acc[j][0], b0.x); t0.y = add2(acc[j][1], b0.y);
        t1.x = add2(acc[j][2], b1.x); t1.y = add2(acc[j][3], b1.y);
        ulonglong2* o = (ulonglong2*)(outx + (size_t)row * 256);
        o[lane] = t0;
        o[lane + 32] = t1;
    }
}

// ---------------------------------------------------------------------------
extern "C" void kernel_launch(void* const* d_in, const int* in_sizes, int n_in,
                              void* d_out, int out_size) {
    const float* x     = (const float*)d_in[0];
    const int*   ei    = (const int*)d_in[1];
    // d_in[2] = edge_attr (unused by reference)
    const float* W_enc = (const float*)d_in[3];
    const float* b_enc = (const float*)d_in[4];
    const float* W_ef  = (const float*)d_in[5];
    const float* b_ef  = (const float*)d_in[6];
    const float* W_df  = (const float*)d_in[7];
    const float* b_df  = (const float*)d_in[8];
    const float* W_dec = (const float*)d_in[9];
    const float* b_dec = (const float*)d_in[10];
    const float* W_c   = (const float*)d_in[11];
    const float* b_c   = (const float*)d_in[12];

    int N = in_sizes[0] / 256;
    int E = in_sizes[1] / 2;
    const int* src = ei;
    const int* dst = ei + E;

    float* out    = (float*)d_out;
    float* out_xr = out;
    float* out_z  = out + (size_t)N * 256;
    float* out_pr = out_z + (size_t)N * 32;

    cudaFuncSetAttribute(k_gemm1, cudaFuncAttributeMaxDynamicSharedMemorySize, 65536);
    cudaFuncSetAttribute(k_gemm2, cudaFuncAttributeMaxDynamicSharedMemorySize, 65536);

    int gbN    = (N + 255) / 256;
    int gbE    = (E + 255) / 256;
    int gbW    = (N + 7) / 8;                   // warp-per-node, 8 warps/block
    int nwarp2 = (N + G2R - 1) / G2R;
    int gbG2   = (nwarp2 * 32 + 255) / 256;
    int nblk   = (N + 1023) / 1024;

    k_count    <<<gbE, 256>>>(dst, E);
    k_scan_a   <<<nblk, 1024>>>(N);
    k_scan_c   <<<gbN, 256>>>(N, nblk);
    k_fill     <<<gbE, 256>>>(src, dst, E);
    k_gemm1    <<<gbN, 256, 65536>>>(x, W_enc, N);
    k_prop1_mlp<<<gbW, 256>>>(b_enc, W_ef, b_ef, W_df, b_df, W_c, b_c, out_z, out_pr, N);
    k_prop_hd  <<<gbW, 256>>>(N);
    k_gemm2    <<<gbG2, 256, 65536>>>(W_dec, b_dec, out_xr, N);
}